// round 11
// baseline (speedup 1.0000x reference)
#include <cuda_runtime.h>
#include <cuda_fp16.h>
#include <cstdint>

#define M_TOK 2048
#define K_IN  4096
#define N_OUT 11008
#define NPACK 1376
#define GSIZE 128
#define NGROUPS 32
#define NTILES 43            // N_OUT / 256

// Scratch (static device globals; no runtime allocation)
__device__ __align__(256) __half   g_xh[(size_t)M_TOK * K_IN];            // 16 MB
__device__ __align__(256) uint32_t g_wp[(size_t)64 * NTILES * 2048];      // 22.5 MB packed int4
__device__ __align__(256) uint32_t g_sz[(size_t)NGROUPS * N_OUT];         // 1.4 MB (s, 1024+z)

// ---------------------------------------------------------------------------
// Kernel 1: x fp32 -> fp16
// ---------------------------------------------------------------------------
__global__ void k_convert_x(const float* __restrict__ x) {
    int i = blockIdx.x * blockDim.x + threadIdx.x;
    const float4* p = reinterpret_cast<const float4*>(x) + (size_t)i * 2;
    float4 v0 = p[0], v1 = p[1];
    __half2 h0 = __floats2half2_rn(v0.x, v0.y);
    __half2 h1 = __floats2half2_rn(v0.z, v0.w);
    __half2 h2 = __floats2half2_rn(v1.x, v1.y);
    __half2 h3 = __floats2half2_rn(v1.z, v1.w);
    uint4 o;
    o.x = *reinterpret_cast<unsigned*>(&h0);
    o.y = *reinterpret_cast<unsigned*>(&h1);
    o.z = *reinterpret_cast<unsigned*>(&h2);
    o.w = *reinterpret_cast<unsigned*>(&h3);
    reinterpret_cast<uint4*>(g_xh)[i] = o;
}

// ---------------------------------------------------------------------------
// Kernel 2: scale/zero side array: g_sz[g][n] = half(s) | half(1024+z)<<16
// ---------------------------------------------------------------------------
__global__ void k_sz(const int* __restrict__ qz, const float* __restrict__ sc) {
    int n = blockIdx.x * 256 + threadIdx.x;
    int g = blockIdx.y;
    unsigned z = ((unsigned)qz[(size_t)g * NPACK + (n >> 3)] >> (4 * (n & 7))) & 0xF;
    __half sh = __float2half_rn(sc[(size_t)g * N_OUT + n]);
    __half zh = __float2half_rn(1024.0f + (float)z);
    g_sz[(size_t)g * N_OUT + n] =
        (uint32_t)__half_as_ushort(sh) | ((uint32_t)__half_as_ushort(zh) << 16);
}

// ---------------------------------------------------------------------------
// Kernel 3: repack qweight into GEMM fragment order (layout unchanged).
// ---------------------------------------------------------------------------
__global__ void k_repack(const int* __restrict__ qw) {
    __shared__ uint32_t sQ[64 * 33];
    int bn = blockIdx.x, kt = blockIdx.y, tid = threadIdx.x;
#pragma unroll
    for (int r = 0; r < 8; r++) {
        int idx = tid + r * 256;
        int row = idx >> 5, col = idx & 31;
        sQ[row * 33 + col] = (uint32_t)qw[(size_t)(kt * 64 + row) * NPACK + bn * 32 + col];
    }
    __syncthreads();
#pragma unroll
    for (int rep = 0; rep < 2; rep++) {
        int pos  = tid + rep * 256;
        int ks   = pos >> 7;
        int wn   = (pos >> 5) & 3;
        int lane = pos & 31;
        int k0   = ks * 16 + (lane & 3) * 2;
        int nib  = lane >> 2;
        uint32_t o[4];
#pragma unroll
        for (int p = 0; p < 4; p++) {
            uint32_t v = 0;
#pragma unroll
            for (int h = 0; h < 2; h++) {
                int c = wn * 8 + 2 * p + h;
#pragma unroll
                for (int dk2 = 0; dk2 < 2; dk2++)
#pragma unroll
                    for (int di = 0; di < 2; di++) {
                        uint32_t nv = (sQ[(k0 + dk2 * 8 + di) * 33 + c] >> (4 * nib)) & 0xFu;
                        v |= nv << (4 * (h * 2 + dk2 + 4 * di));
                    }
            }
            o[p] = v;
        }
        *reinterpret_cast<uint4*>(&g_wp[((size_t)kt * NTILES + bn) * 2048 + pos * 4]) =
            make_uint4(o[0], o[1], o[2], o[3]);
    }
}

// ---------------------------------------------------------------------------
// Kernel 4: fused int4 GEMM. BM=128 BN=256 BK=64, 512 threads,
// 16 warps (4m x 4n), warp tile 32x64, 6-stage cp.async.
// ---------------------------------------------------------------------------
#define BM 128
#define BN 256
#define BK 64
#define NSTAGES 6
#define KT (K_IN / BK)                 // 64
#define PA 72                          // A pitch (halves)
#define ABYTES (BM * PA * 2)           // 18432
#define BBYTES 8192
#define STAGE_BYTES (ABYTES + BBYTES)  // 26624
#define SMEM_BYTES (NSTAGES * STAGE_BYTES)  // 159744

__device__ __forceinline__ unsigned smem_u32(const void* p) {
    return (unsigned)__cvta_generic_to_shared(p);
}
__device__ __forceinline__ uint32_t dq1(uint32_t t, uint32_t z2, uint32_t s2) {
    __half2 r = __hmul2(__hsub2(*reinterpret_cast<__half2*>(&t),
                                *reinterpret_cast<const __half2*>(&z2)),
                        *reinterpret_cast<const __half2*>(&s2));
    return *reinterpret_cast<uint32_t*>(&r);
}

__global__ __launch_bounds__(512, 1)
void k_gemm(const float* __restrict__ bias, float* __restrict__ out) {
    extern __shared__ __align__(16) char sm[];

    const int tid  = threadIdx.x;
    const int bm   = blockIdx.x;       // 16 m-tiles (fast: wave shares B)
    const int bn   = blockIdx.y;       // 43 n-tiles
    const int warp = tid >> 5;
    const int lane = tid & 31;
    const int wm   = warp & 3;         // 4 m groups of 32 rows
    const int wn   = warp >> 2;        // 4 n groups of 64 cols
    const int mat  = lane >> 3;
    const int lr   = lane & 7;

    const __half* gA = g_xh + (size_t)bm * BM * K_IN;

    auto load_stage = [&](int kt, int s) {
        char* base = sm + s * STAGE_BYTES;
        __half* As = reinterpret_cast<__half*>(base);
#pragma unroll
        for (int r = 0; r < 2; r++) {               // A: 1024 chunks of 16B
            int ch  = tid + r * 512;
            int row = ch >> 3, cc = ch & 7;
            const __half* src = gA + (size_t)row * K_IN + kt * BK + cc * 8;
            unsigned dst = smem_u32(As + row * PA + cc * 8);
            asm volatile("cp.async.cg.shared.global [%0], [%1], 16;\n"
                         :: "r"(dst), "l"(src));
        }
        const char* srcB = reinterpret_cast<const char*>(g_wp) +
                           ((size_t)kt * NTILES + bn) * BBYTES + tid * 16;
        unsigned dstB = smem_u32(base + ABYTES + tid * 16);
        asm volatile("cp.async.cg.shared.global [%0], [%1], 16;\n"
                     :: "r"(dstB), "l"(srcB));
        asm volatile("cp.async.commit_group;\n");
    };

    float acc[2][8][4];
#pragma unroll
    for (int i = 0; i < 2; i++)
#pragma unroll
        for (int j = 0; j < 8; j++)
#pragma unroll
            for (int l = 0; l < 4; l++) acc[i][j][l] = 0.0f;

    // Prologue: fill NSTAGES-1 stages
#pragma unroll
    for (int s = 0; s < NSTAGES - 1; s++) load_stage(s, s);

    const uint32_t* szbase = g_sz + (size_t)bn * BN + wn * 64 + (lane >> 2);

    for (int kt = 0; kt < KT; kt++) {
        asm volatile("cp.async.wait_group %0;\n" :: "n"(NSTAGES - 2));
        __syncthreads();

        if (kt + NSTAGES - 1 < KT)
            load_stage(kt + NSTAGES - 1, (kt + NSTAGES - 1) % NSTAGES);
        else
            asm volatile("cp.async.commit_group;\n");

        char* base = sm + (kt % NSTAGES) * STAGE_BYTES;
        __half* As = reinterpret_cast<__half*>(base);
        unsigned bq_base = smem_u32(base + ABYTES);

        // scale/zero for this group (broadcast half2s), reloaded per chunk (L1 hit)
        uint32_t s2[8], z2[8];
        {
            const uint32_t* szp = szbase + (size_t)(kt >> 1) * N_OUT;
#pragma unroll
            for (int j = 0; j < 8; j++) {
                uint32_t v = __ldg(szp + 8 * j);
                s2[j] = __byte_perm(v, v, 0x1010);
                z2[j] = __byte_perm(v, v, 0x3232);
            }
        }

        unsigned a[2][2][4];
        uint32_t q[2][4];

        auto ld_a = [&](int ks, unsigned (*af)[4]) {
#pragma unroll
            for (int mt = 0; mt < 2; mt++) {
                int row = wm * 32 + mt * 16 + (mat & 1) * 8 + lr;
                int col = ks * 16 + (mat >> 1) * 8;
                unsigned addr = smem_u32(As + row * PA + col);
                asm volatile(
                    "ldmatrix.sync.aligned.m8n8.x4.shared.b16 {%0,%1,%2,%3}, [%4];\n"
                    : "=r"(af[mt][0]), "=r"(af[mt][1]), "=r"(af[mt][2]), "=r"(af[mt][3])
                    : "r"(addr));
            }
        };
        auto ld_q = [&](int ks, uint32_t* qq) {
            unsigned addr = bq_base + ((ks * 4 + wn) * 32 + lane) * 16;
            asm volatile("ld.shared.v4.u32 {%0,%1,%2,%3}, [%4];\n"
                         : "=r"(qq[0]), "=r"(qq[1]), "=r"(qq[2]), "=r"(qq[3])
                         : "r"(addr));
        };

        ld_a(0, a[0]);
        ld_q(0, q[0]);
#pragma unroll
        for (int ks = 0; ks < 4; ks++) {
            if (ks < 3) { ld_a(ks + 1, a[(ks + 1) & 1]); ld_q(ks + 1, q[(ks + 1) & 1]); }

            // Dequant B fragments for this ks
            uint32_t bfr[8][2];
            const uint32_t* qq = q[ks & 1];
#pragma unroll
            for (int p = 0; p < 4; p++) {
                uint32_t qp = qq[p];
#pragma unroll
                for (int h = 0; h < 2; h++) {
                    int j = 2 * p + h;
                    uint32_t t0 = ((qp >> (8 * h))     & 0x000f000fu) | 0x64006400u;
                    uint32_t t1 = ((qp >> (8 * h + 4)) & 0x000f000fu) | 0x64006400u;
                    bfr[j][0] = dq1(t0, z2[j], s2[j]);
                    bfr[j][1] = dq1(t1, z2[j], s2[j]);
                }
            }

            unsigned (*af)[4] = a[ks & 1];
#pragma unroll
            for (int mt = 0; mt < 2; mt++)
#pragma unroll
                for (int nt = 0; nt < 8; nt++) {
                    float* d = acc[mt][nt];
                    asm volatile(
                        "mma.sync.aligned.m16n8k16.row.col.f32.f16.f16.f32 "
                        "{%0,%1,%2,%3},{%4,%5,%6,%7},{%8,%9},{%0,%1,%2,%3};\n"
                        : "+f"(d[0]), "+f"(d[1]), "+f"(d[2]), "+f"(d[3])
                        : "r"(af[mt][0]), "r"(af[mt][1]), "r"(af[mt][2]), "r"(af[mt][3]),
                          "r"(bfr[nt][0]), "r"(bfr[nt][1]));
                }
        }
        __syncthreads();
    }

    // Epilogue: add bias, store fp32.
#pragma unroll
    for (int nt = 0; nt < 8; nt++) {
        int col = bn * BN + wn * 64 + nt * 8 + (lane & 3) * 2;
        float2 bv = *reinterpret_cast<const float2*>(bias + col);
#pragma unroll
        for (int mt = 0; mt < 2; mt++) {
            int row = bm * BM + wm * 32 + mt * 16 + (lane >> 2);
            float2 o0 = make_float2(acc[mt][nt][0] + bv.x, acc[mt][nt][1] + bv.y);
            float2 o1 = make_float2(acc[mt][nt][2] + bv.x, acc[mt][nt][3] + bv.y);
            *reinterpret_cast<float2*>(out + (size_t)row * N_OUT + col)       = o0;
            *reinterpret_cast<float2*>(out + (size_t)(row + 8) * N_OUT + col) = o1;
        }
    }
}

// ---------------------------------------------------------------------------
// Launch
// ---------------------------------------------------------------------------
extern "C" void kernel_launch(void* const* d_in, const int* in_sizes, int n_in,
                              void* d_out, int out_size) {
    const float* x    = (const float*)d_in[0];
    const int*   qw   = (const int*)d_in[1];
    const int*   qz   = (const int*)d_in[2];
    const float* sc   = (const float*)d_in[3];
    const float* bias = (const float*)d_in[4];
    float* out = (float*)d_out;

    k_convert_x<<<(M_TOK * K_IN / 8) / 256, 256>>>(x);

    dim3 gsz(NTILES, NGROUPS);
    k_sz<<<gsz, 256>>>(qz, sc);

    dim3 grp(NTILES, KT);
    k_repack<<<grp, 256>>>(qw);

    static bool attr_set = false;
    if (!attr_set) {
        cudaFuncSetAttribute(k_gemm, cudaFuncAttributeMaxDynamicSharedMemorySize,
                             SMEM_BYTES);
        attr_set = true;
    }
    dim3 grid(M_TOK / BM, N_OUT / BN);   // (16, 43)
    k_gemm<<<grid, 512, SMEM_BYTES>>>(bias, out);
}

// round 13
// speedup vs baseline: 1.1796x; 1.1796x over previous
#include <cuda_runtime.h>
#include <cuda_fp16.h>
#include <cstdint>

#define M_TOK 2048
#define K_IN  4096
#define N_OUT 11008
#define NPACK 1376
#define GSIZE 128
#define NGROUPS 32
#define NTILES 43            // N_OUT / 256

// Scratch (static device globals; no runtime allocation)
__device__ __align__(256) __half   g_xh[(size_t)M_TOK * K_IN];            // 16 MB
__device__ __align__(256) uint32_t g_wp[(size_t)64 * NTILES * 2048];      // 22.5 MB packed int4
__device__ __align__(256) uint32_t g_sz[(size_t)NGROUPS * N_OUT];         // 1.4 MB (s, 1024+z)

// ---------------------------------------------------------------------------
// Kernel 1: x fp32 -> fp16
// ---------------------------------------------------------------------------
__global__ void k_convert_x(const float* __restrict__ x) {
    int i = blockIdx.x * blockDim.x + threadIdx.x;
    const float4* p = reinterpret_cast<const float4*>(x) + (size_t)i * 2;
    float4 v0 = p[0], v1 = p[1];
    __half2 h0 = __floats2half2_rn(v0.x, v0.y);
    __half2 h1 = __floats2half2_rn(v0.z, v0.w);
    __half2 h2 = __floats2half2_rn(v1.x, v1.y);
    __half2 h3 = __floats2half2_rn(v1.z, v1.w);
    uint4 o;
    o.x = *reinterpret_cast<unsigned*>(&h0);
    o.y = *reinterpret_cast<unsigned*>(&h1);
    o.z = *reinterpret_cast<unsigned*>(&h2);
    o.w = *reinterpret_cast<unsigned*>(&h3);
    reinterpret_cast<uint4*>(g_xh)[i] = o;
}

// ---------------------------------------------------------------------------
// Kernel 2: scale/zero side array: g_sz[g][n] = half(s) | half(1024+z)<<16
// ---------------------------------------------------------------------------
__global__ void k_sz(const int* __restrict__ qz, const float* __restrict__ sc) {
    int n = blockIdx.x * 256 + threadIdx.x;
    int g = blockIdx.y;
    unsigned z = ((unsigned)qz[(size_t)g * NPACK + (n >> 3)] >> (4 * (n & 7))) & 0xF;
    __half sh = __float2half_rn(sc[(size_t)g * N_OUT + n]);
    __half zh = __float2half_rn(1024.0f + (float)z);
    g_sz[(size_t)g * N_OUT + n] =
        (uint32_t)__half_as_ushort(sh) | ((uint32_t)__half_as_ushort(zh) << 16);
}

// ---------------------------------------------------------------------------
// Kernel 3: repack qweight for the 64x32-warp-tile GEMM.
// Layout: [kt(64)][bn(43)][ pos = (ks*8+wn)*32+lane ][2 x u32].
// Lane's 2 u32 cover nt=0..3 (4 n8 fragments, n = wn*32+nt*8+lane/4):
//   u32 u: nib0=A(2u) nib1=C(2u) nib2=A(2u+1) nib3=C(2u+1)
//          nib4=B(2u) nib5=D(2u) nib6=B(2u+1) nib7=D(2u+1)
//   where A=w[k0][n], B=w[k0+1][n], C=w[k0+8][n], D=w[k0+9][n],
//   k0 = ks*16 + (lane%4)*2.
// ---------------------------------------------------------------------------
__global__ void k_repack(const int* __restrict__ qw) {
    __shared__ uint32_t sQ[64 * 33];
    int bn = blockIdx.x, kt = blockIdx.y, tid = threadIdx.x;
#pragma unroll
    for (int r = 0; r < 8; r++) {
        int idx = tid + r * 256;
        int row = idx >> 5, col = idx & 31;
        sQ[row * 33 + col] = (uint32_t)qw[(size_t)(kt * 64 + row) * NPACK + bn * 32 + col];
    }
    __syncthreads();
#pragma unroll
    for (int rep = 0; rep < 4; rep++) {
        int pos  = tid + rep * 256;
        int ks   = pos >> 8;
        int wn   = (pos >> 5) & 7;
        int lane = pos & 31;
        int k0   = ks * 16 + (lane & 3) * 2;
        int sh   = 4 * (lane >> 2);
        uint32_t v[2];
#pragma unroll
        for (int u = 0; u < 2; u++) {
            int pc0 = wn * 4 + 2 * u, pc1 = pc0 + 1;
#define NB(kk, cc) ((sQ[(kk) * 33 + (cc)] >> sh) & 0xFu)
            v[u] =  NB(k0,     pc0)        | (NB(k0 + 8, pc0) << 4)
                 | (NB(k0,     pc1) << 8)  | (NB(k0 + 8, pc1) << 12)
                 | (NB(k0 + 1, pc0) << 16) | (NB(k0 + 9, pc0) << 20)
                 | (NB(k0 + 1, pc1) << 24) | (NB(k0 + 9, pc1) << 28);
#undef NB
        }
        *reinterpret_cast<uint2*>(&g_wp[((size_t)kt * NTILES + bn) * 2048 + pos * 2]) =
            make_uint2(v[0], v[1]);
    }
}

// ---------------------------------------------------------------------------
// Kernel 4: fused int4 GEMM. BM=128 BN=256 BK=64, 512 threads,
// 16 warps (2 wm x 8 wn), warp tile 64x32, 6-stage cp.async.
// ---------------------------------------------------------------------------
#define BM 128
#define BN 256
#define BK 64
#define NSTAGES 6
#define KT (K_IN / BK)                 // 64
#define PA 72                          // A pitch (halves)
#define ABYTES (BM * PA * 2)           // 18432
#define BBYTES 8192
#define STAGE_BYTES (ABYTES + BBYTES)  // 26624
#define SMEM_BYTES (NSTAGES * STAGE_BYTES)  // 159744

__device__ __forceinline__ unsigned smem_u32(const void* p) {
    return (unsigned)__cvta_generic_to_shared(p);
}
__device__ __forceinline__ uint32_t dq1(uint32_t t, uint32_t z2, uint32_t s2) {
    __half2 r = __hmul2(__hsub2(*reinterpret_cast<__half2*>(&t),
                                *reinterpret_cast<const __half2*>(&z2)),
                        *reinterpret_cast<const __half2*>(&s2));
    return *reinterpret_cast<uint32_t*>(&r);
}

__global__ __launch_bounds__(512, 1)
void k_gemm(const float* __restrict__ bias, float* __restrict__ out) {
    extern __shared__ __align__(16) char sm[];

    const int tid  = threadIdx.x;
    const int bm   = blockIdx.x;       // 16 m-tiles (fast: wave shares B)
    const int bn   = blockIdx.y;       // 43 n-tiles
    const int warp = tid >> 5;
    const int lane = tid & 31;
    const int wm   = warp & 1;         // 2 m groups of 64 rows
    const int wn   = warp >> 1;        // 8 n groups of 32 cols
    const int mat  = lane >> 3;
    const int lr   = lane & 7;

    const __half* gA = g_xh + (size_t)bm * BM * K_IN;

    auto load_stage = [&](int kt, int s) {
        char* base = sm + s * STAGE_BYTES;
        __half* As = reinterpret_cast<__half*>(base);
#pragma unroll
        for (int r = 0; r < 2; r++) {               // A: 1024 chunks of 16B
            int ch  = tid + r * 512;
            int row = ch >> 3, cc = ch & 7;
            const __half* src = gA + (size_t)row * K_IN + kt * BK + cc * 8;
            unsigned dst = smem_u32(As + row * PA + cc * 8);
            asm volatile("cp.async.cg.shared.global [%0], [%1], 16;\n"
                         :: "r"(dst), "l"(src));
        }
        const char* srcB = reinterpret_cast<const char*>(g_wp) +
                           ((size_t)kt * NTILES + bn) * BBYTES + tid * 16;
        unsigned dstB = smem_u32(base + ABYTES + tid * 16);
        asm volatile("cp.async.cg.shared.global [%0], [%1], 16;\n"
                     :: "r"(dstB), "l"(srcB));
        asm volatile("cp.async.commit_group;\n");
    };

    float acc[4][4][4];
#pragma unroll
    for (int i = 0; i < 4; i++)
#pragma unroll
        for (int j = 0; j < 4; j++)
#pragma unroll
            for (int l = 0; l < 4; l++) acc[i][j][l] = 0.0f;

    // Prologue: fill NSTAGES-1 stages
#pragma unroll
    for (int s = 0; s < NSTAGES - 1; s++) load_stage(s, s);

    const uint32_t* szbase = g_sz + (size_t)bn * BN + wn * 32 + (lane >> 2);

    for (int kt = 0; kt < KT; kt++) {
        asm volatile("cp.async.wait_group %0;\n" :: "n"(NSTAGES - 2));
        __syncthreads();

        if (kt + NSTAGES - 1 < KT)
            load_stage(kt + NSTAGES - 1, (kt + NSTAGES - 1) % NSTAGES);
        else
            asm volatile("cp.async.commit_group;\n");

        char* base = sm + (kt % NSTAGES) * STAGE_BYTES;
        __half* As = reinterpret_cast<__half*>(base);
        unsigned bq_base = smem_u32(base + ABYTES);

        // All 4 ks worth of packed B for this warp/lane: 4 x LDS.64
        uint32_t q[8];
#pragma unroll
        for (int ks = 0; ks < 4; ks++) {
            unsigned addr = bq_base + ((ks * 8 + wn) * 32 + lane) * 8;
            asm volatile("ld.shared.v2.u32 {%0,%1}, [%2];\n"
                         : "=r"(q[2 * ks]), "=r"(q[2 * ks + 1]) : "r"(addr));
        }

        // scale/zero for this group (4 n8 fragments)
        uint32_t s2[4], z2[4];
        {
            const uint32_t* szp = szbase + (size_t)(kt >> 1) * N_OUT;
#pragma unroll
            for (int j = 0; j < 4; j++) {
                uint32_t v = __ldg(szp + 8 * j);
                s2[j] = __byte_perm(v, v, 0x1010);
                z2[j] = __byte_perm(v, v, 0x3232);
            }
        }

#pragma unroll
        for (int ks = 0; ks < 4; ks++) {
            // A fragments for this ks (4 x ldmatrix.x4, issued first)
            unsigned af[4][4];
#pragma unroll
            for (int mt = 0; mt < 4; mt++) {
                int row = wm * 64 + mt * 16 + (mat & 1) * 8 + lr;
                int col = ks * 16 + (mat >> 1) * 8;
                unsigned addr = smem_u32(As + row * PA + col);
                asm volatile(
                    "ldmatrix.sync.aligned.m8n8.x4.shared.b16 {%0,%1,%2,%3}, [%4];\n"
                    : "=r"(af[mt][0]), "=r"(af[mt][1]), "=r"(af[mt][2]), "=r"(af[mt][3])
                    : "r"(addr));
            }

            // Dequant 4 B fragments (8 regs) from 2 packed u32
            uint32_t bfr[4][2];
#pragma unroll
            for (int u = 0; u < 2; u++) {
                uint32_t qp = q[2 * ks + u];
                uint32_t t0 = ( qp        & 0x000f000fu) | 0x64006400u;
                uint32_t t1 = ((qp >> 4)  & 0x000f000fu) | 0x64006400u;
                uint32_t t2 = ((qp >> 8)  & 0x000f000fu) | 0x64006400u;
                uint32_t t3 = ((qp >> 12) & 0x000f000fu) | 0x64006400u;
                bfr[2 * u][0]     = dq1(t0, z2[2 * u],     s2[2 * u]);
                bfr[2 * u][1]     = dq1(t1, z2[2 * u],     s2[2 * u]);
                bfr[2 * u + 1][0] = dq1(t2, z2[2 * u + 1], s2[2 * u + 1]);
                bfr[2 * u + 1][1] = dq1(t3, z2[2 * u + 1], s2[2 * u + 1]);
            }

#pragma unroll
            for (int mt = 0; mt < 4; mt++)
#pragma unroll
                for (int nt = 0; nt < 4; nt++) {
                    float* d = acc[mt][nt];
                    asm volatile(
                        "mma.sync.aligned.m16n8k16.row.col.f32.f16.f16.f32 "
                        "{%0,%1,%2,%3},{%4,%5,%6,%7},{%8,%9},{%0,%1,%2,%3};\n"
                        : "+f"(d[0]), "+f"(d[1]), "+f"(d[2]), "+f"(d[3])
                        : "r"(af[mt][0]), "r"(af[mt][1]), "r"(af[mt][2]), "r"(af[mt][3]),
                          "r"(bfr[nt][0]), "r"(bfr[nt][1]));
                }
        }
        __syncthreads();
    }

    // Epilogue: add bias, store fp32.
#pragma unroll
    for (int nt = 0; nt < 4; nt++) {
        int col = bn * BN + wn * 32 + nt * 8 + (lane & 3) * 2;
        float2 bv = *reinterpret_cast<const float2*>(bias + col);
#pragma unroll
        for (int mt = 0; mt < 4; mt++) {
            int row = bm * BM + wm * 64 + mt * 16 + (lane >> 2);
            float2 o0 = make_float2(acc[mt][nt][0] + bv.x, acc[mt][nt][1] + bv.y);
            float2 o1 = make_float2(acc[mt][nt][2] + bv.x, acc[mt][nt][3] + bv.y);
            *reinterpret_cast<float2*>(out + (size_t)row * N_OUT + col)       = o0;
            *reinterpret_cast<float2*>(out + (size_t)(row + 8) * N_OUT + col) = o1;
        }
    }
}

// ---------------------------------------------------------------------------
// Launch
// ---------------------------------------------------------------------------
extern "C" void kernel_launch(void* const* d_in, const int* in_sizes, int n_in,
                              void* d_out, int out_size) {
    const float* x    = (const float*)d_in[0];
    const int*   qw   = (const int*)d_in[1];
    const int*   qz   = (const int*)d_in[2];
    const float* sc   = (const float*)d_in[3];
    const float* bias = (const float*)d_in[4];
    float* out = (float*)d_out;

    k_convert_x<<<(M_TOK * K_IN / 8) / 256, 256>>>(x);

    dim3 gsz(NTILES, NGROUPS);
    k_sz<<<gsz, 256>>>(qz, sc);

    dim3 grp(NTILES, KT);
    k_repack<<<grp, 256>>>(qw);

    static bool attr_set = false;
    if (!attr_set) {
        cudaFuncSetAttribute(k_gemm, cudaFuncAttributeMaxDynamicSharedMemorySize,
                             SMEM_BYTES);
        attr_set = true;
    }
    dim3 grid(M_TOK / BM, N_OUT / BN);   // (16, 43)
    k_gemm<<<grid, 512, SMEM_BYTES>>>(bias, out);
}